// round 7
// baseline (speedup 1.0000x reference)
#include <cuda_runtime.h>
#include <math.h>

#define NP 512
#define ND 3
#define NK 32
#define NT 10
#define NB 8
#define EPSF 1e-6f
#define NBLOCKS (NP * NB)
#define NBUILD 32
#define TPB 128

#define NTAB 8192
#define DRANGE 4.0f
#define TSCALE ((float)NTAB / DRANGE)

__device__ float2   g_tab[NTAB];         // (fm(d), dfm(d))
__device__ float    g_divpart[NB * NP];
__device__ unsigned g_count  = 0;
__device__ unsigned g_tabcnt = 0;

__device__ __forceinline__ unsigned ld_acq(const unsigned* p) {
    unsigned v;
    asm volatile("ld.global.acquire.gpu.b32 %0, [%1];" : "=r"(v) : "l"(p) : "memory");
    return v;
}

// Coherent L2 load of a table entry (NOT the nc path — table is written this launch).
__device__ __forceinline__ float2 ld_tab(const float2* p) {
    float2 v;
    asm volatile("ld.global.cg.v2.f32 {%0, %1}, [%2];"
                 : "=f"(v.x), "=f"(v.y) : "l"(p) : "memory");
    return v;
}

__global__ void __launch_bounds__(TPB) fused_kernel(
    const float* __restrict__ t_in,
    const float* __restrict__ x,
    const float* __restrict__ mus,
    const float* __restrict__ nlg,
    const float* __restrict__ mus_t,
    const float* __restrict__ nlg_t,
    const float* __restrict__ W,
    const float* __restrict__ bias,
    const float* __restrict__ imp,
    float* __restrict__ out)
{
    __shared__ float s_mu[NK], s_ig2[NK], s_w[NK];
    __shared__ float s_cadd;
    __shared__ float red[4][4];
    __shared__ float res[4];
    __shared__ int   s_last;

    const int bid = blockIdx.x;
    const int tid = threadIdx.x;
    const int i = bid & (NP - 1);
    const int b = bid >> 9;

    // ---- hoist pair position loads (independent of the table) ----
    const float* xb = x + b * (NP * ND);
    const float xi0 = xb[i * 3 + 0];
    const float xi1 = xb[i * 3 + 1];
    const float xi2 = xb[i * 3 + 2];
    float rx[4], ry[4], rz[4], dd[4];
#pragma unroll
    for (int q = 0; q < 4; q++) {
        const int j = tid + q * TPB;
        rx[q] = xi0 - xb[j * 3 + 0];
        ry[q] = xi1 - xb[j * 3 + 1];
        rz[q] = xi2 - xb[j * 3 + 2];
        float d2s = fmaf(rx[q], rx[q], fmaf(ry[q], ry[q], fmaf(rz[q], rz[q], EPSF)));
        asm("sqrt.approx.ftz.f32 %0, %1;" : "=f"(dd[q]) : "f"(d2s));
    }

    // ---- builder blocks (first 32 bids, wave-1 resident): weights + table slice ----
    if (bid < NBUILD) {
        if (tid < NK) {
            const int k = tid;
            const float t = t_in[0];
            float tr[NT];
            float ssum = 0.f;
#pragma unroll
            for (int q = 0; q < NT; q++) {
                float ig = __expf(nlg_t[q]);
                float df = t - mus_t[q];
                float v  = __expf(-df * df * ig * ig);
                tr[q] = v;
                ssum += v;
            }
            const float invs = 1.0f / (EPSF + ssum);

            float w = 0.f;
#pragma unroll
            for (int q = 0; q < NT; q++) w = fmaf(W[k * NT + q], tr[q], w);
            w *= invs;

            float v = imp[k] * imp[k] * w;
#pragma unroll
            for (int o = 16; o; o >>= 1) v += __shfl_down_sync(0xffffffffu, v, o);

            float ig = __expf(nlg[k]);
            s_mu[k]  = mus[k];
            s_ig2[k] = ig * ig;
            s_w[k]   = w;
            if (k == 0) {
                float cadd = v;
#pragma unroll
                for (int q = 0; q < NT; q++) cadd = fmaf(bias[q] * invs, tr[q], cadd);
                s_cadd = cadd;
            }
        }
        __syncthreads();

        const float cadd = s_cadd;
#pragma unroll
        for (int q = 0; q < 2; q++) {
            const int idx = bid * 256 + q * TPB + tid;
            const float d = (float)idx * (DRANGE / (float)NTAB);
            float S0 = 0.f, W0 = 0.f, SD = 0.f, SDW = 0.f;
#pragma unroll 8
            for (int k = 0; k < NK; k++) {
                float diff = d - s_mu[k];
                float ig2  = s_ig2[k];
                float r  = __expf(-diff * diff * ig2);
                float dr = -2.f * diff * ig2 * r;
                S0  += r;
                W0   = fmaf(r,  s_w[k], W0);
                SD  += dr;
                SDW  = fmaf(dr, s_w[k], SDW);
            }
            const float inv = 1.0f / (EPSF + S0);
            float2 e;
            e.x = fmaf(W0, inv, cadd);
            e.y = (SDW - W0 * SD * inv) * inv;
            g_tab[idx] = e;
        }
        __threadfence();
        __syncthreads();
        if (tid == 0) atomicAdd(&g_tabcnt, 1u);
    }

    // ---- gate: wait until all 32 table slices are published ----
    if (tid == 0) {
        while (ld_acq(&g_tabcnt) < NBUILD) __nanosleep(64);
    }
    __syncthreads();

    // ---- pair work: table lookups + accumulate ----
    float fx = 0.f, fy = 0.f, fz = 0.f, dv = 0.f;

#pragma unroll
    for (int q = 0; q < 4; q++) {
        const int j = tid + q * TPB;
        const float d = dd[q];
        float u = d * TSCALE;
        int i0 = (int)u;
        i0 = min(i0, NTAB - 2);
        float frac = u - (float)i0;
        const float2 e0 = ld_tab(&g_tab[i0]);
        const float2 e1 = ld_tab(&g_tab[i0 + 1]);
        float fm  = fmaf(frac, e1.x - e0.x, e0.x);
        float dfm = fmaf(frac, e1.y - e0.y, e0.y);

        if (j == i) { fm = 0.f; dfm = 0.f; }   // remove_diagonal

        fx = fmaf(rx[q], fm, fx);
        fy = fmaf(ry[q], fm, fy);
        fz = fmaf(rz[q], fm, fz);
        dv += fmaf(d, dfm, 3.f * fm);
    }

    // ---- block reduction (4 warps) ----
    const unsigned m = 0xffffffffu;
#pragma unroll
    for (int o = 16; o; o >>= 1) {
        fx += __shfl_down_sync(m, fx, o);
        fy += __shfl_down_sync(m, fy, o);
        fz += __shfl_down_sync(m, fz, o);
        dv += __shfl_down_sync(m, dv, o);
    }
    const int warp = tid >> 5;
    const int lane = tid & 31;
    if (lane == 0) {
        red[warp][0] = fx; red[warp][1] = fy; red[warp][2] = fz; red[warp][3] = dv;
    }
    __syncthreads();
    if (tid < 16) {
        float v = red[tid & 3][tid >> 2];
        v += __shfl_down_sync(0xffffu, v, 1);
        v += __shfl_down_sync(0xffffu, v, 2);
        if ((tid & 3) == 0) res[tid >> 2] = v;
    }
    __syncthreads();
    if (tid == 0) {
        float* fo = out + b * (NP * ND) + i * 3;
        fo[0] = res[0]; fo[1] = res[1]; fo[2] = res[2];
        g_divpart[b * NP + i] = res[3];
        __threadfence();
        unsigned old = atomicInc(&g_count, NBLOCKS - 1);
        s_last = (old == NBLOCKS - 1) ? 1 : 0;
    }
    __syncthreads();

    // ---- last block: deterministic divergence reduction + counter reset ----
    if (s_last) {
        __threadfence();
        if (tid == 0) g_tabcnt = 0;   // reset for next graph replay
        const int bb = tid >> 4;   // 0..7
        const int l  = tid & 15;
        float v = 0.f;
#pragma unroll
        for (int c = 0; c < 32; c++)
            v += __ldcg(&g_divpart[bb * NP + l * 32 + c]);
#pragma unroll
        for (int o = 8; o; o >>= 1) v += __shfl_down_sync(m, v, o, 16);
        if (l == 0) out[NB * NP * ND + bb] = -v;
    }
}

extern "C" void kernel_launch(void* const* d_in, const int* in_sizes, int n_in,
                              void* d_out, int out_size)
{
    const float* t_in  = (const float*)d_in[0];
    const float* x     = (const float*)d_in[1];
    const float* mus   = (const float*)d_in[2];
    const float* nlg   = (const float*)d_in[3];
    const float* mus_t = (const float*)d_in[4];
    const float* nlg_t = (const float*)d_in[5];
    const float* W     = (const float*)d_in[6];
    const float* bias  = (const float*)d_in[7];
    const float* imp   = (const float*)d_in[8];
    float* out = (float*)d_out;

    fused_kernel<<<NBLOCKS, TPB>>>(t_in, x, mus, nlg, mus_t, nlg_t, W, bias, imp, out);
}

// round 8
// speedup vs baseline: 2.1586x; 2.1586x over previous
#include <cuda_runtime.h>
#include <math.h>

#define NP 512
#define ND 3
#define NK 32
#define NT 10
#define NB 8
#define EPSF 1e-6f
#define NBLOCKS (NP * NB)
#define TPB 128

#define NTAB 8192
#define DRANGE 4.0f
#define TSCALE ((float)NTAB / DRANGE)

__device__ float2   g_tab[NTAB];         // (fm(d), dfm(d))
__device__ float    g_divpart[NB * NP];
__device__ unsigned g_count = 0;

// ---- launch 1: 32 blocks; each redundantly computes weights, fills its table slice ----
__global__ void __launch_bounds__(TPB) build_table_kernel(
    const float* __restrict__ t_in,
    const float* __restrict__ mus,
    const float* __restrict__ nlg,
    const float* __restrict__ mus_t,
    const float* __restrict__ nlg_t,
    const float* __restrict__ W,
    const float* __restrict__ bias,
    const float* __restrict__ imp)
{
    __shared__ float s_mu[NK], s_ig2[NK], s_w[NK];
    __shared__ float s_cadd;

    const int bid = blockIdx.x;
    const int tid = threadIdx.x;

    if (tid < NK) {
        const int k = tid;
        const float t = t_in[0];
        float tr[NT];
        float ssum = 0.f;
#pragma unroll
        for (int q = 0; q < NT; q++) {
            float ig = __expf(nlg_t[q]);
            float df = t - mus_t[q];
            float v  = __expf(-df * df * ig * ig);
            tr[q] = v;
            ssum += v;
        }
        const float invs = 1.0f / (EPSF + ssum);

        float w = 0.f;
#pragma unroll
        for (int q = 0; q < NT; q++) w = fmaf(W[k * NT + q], tr[q], w);
        w *= invs;

        float v = imp[k] * imp[k] * w;
#pragma unroll
        for (int o = 16; o; o >>= 1) v += __shfl_down_sync(0xffffffffu, v, o);

        float ig = __expf(nlg[k]);
        s_mu[k]  = mus[k];
        s_ig2[k] = ig * ig;
        s_w[k]   = w;
        if (k == 0) {
            float cadd = v;
#pragma unroll
            for (int q = 0; q < NT; q++) cadd = fmaf(bias[q] * invs, tr[q], cadd);
            s_cadd = cadd;
        }
    }
    __syncthreads();

    const float cadd = s_cadd;
#pragma unroll
    for (int q = 0; q < 2; q++) {
        const int idx = bid * 256 + q * TPB + tid;
        const float d = (float)idx * (DRANGE / (float)NTAB);
        float S0 = 0.f, W0 = 0.f, SD = 0.f, SDW = 0.f;
#pragma unroll 8
        for (int k = 0; k < NK; k++) {
            float diff = d - s_mu[k];
            float ig2  = s_ig2[k];
            float r  = __expf(-diff * diff * ig2);
            float dr = -2.f * diff * ig2 * r;
            S0  += r;
            W0   = fmaf(r,  s_w[k], W0);
            SD  += dr;
            SDW  = fmaf(dr, s_w[k], SDW);
        }
        const float inv = 1.0f / (EPSF + S0);
        float2 e;
        e.x = fmaf(W0, inv, cadd);          // fm
        e.y = (SDW - W0 * SD * inv) * inv;  // dfm
        g_tab[idx] = e;
    }
}

// ---- launch 2: pair kernel. block=(i,b), 128 threads, 4 j's per thread ----
__global__ void __launch_bounds__(TPB) pair_kernel(const float* __restrict__ x,
                                                   float* __restrict__ out)
{
    __shared__ float red[4][4];
    __shared__ float res[4];
    __shared__ int   s_last;

    const int tid = threadIdx.x;
    const int i = blockIdx.x;
    const int b = blockIdx.y;

    const float* xb = x + b * (NP * ND);
    const float xi0 = xb[i * 3 + 0];
    const float xi1 = xb[i * 3 + 1];
    const float xi2 = xb[i * 3 + 2];

    float fx = 0.f, fy = 0.f, fz = 0.f, dv = 0.f;

#pragma unroll
    for (int q = 0; q < 4; q++) {
        const int j = tid + q * TPB;
        const float rx = xi0 - xb[j * 3 + 0];
        const float ry = xi1 - xb[j * 3 + 1];
        const float rz = xi2 - xb[j * 3 + 2];
        float d2s = fmaf(rx, rx, fmaf(ry, ry, fmaf(rz, rz, EPSF)));
        float d;
        asm("sqrt.approx.ftz.f32 %0, %1;" : "=f"(d) : "f"(d2s));

        float u = d * TSCALE;
        int i0 = (int)u;
        i0 = min(i0, NTAB - 2);
        float frac = u - (float)i0;
        const float2 e0 = __ldg(&g_tab[i0]);
        const float2 e1 = __ldg(&g_tab[i0 + 1]);
        float fm  = fmaf(frac, e1.x - e0.x, e0.x);
        float dfm = fmaf(frac, e1.y - e0.y, e0.y);

        if (j == i) { fm = 0.f; dfm = 0.f; }   // remove_diagonal

        fx = fmaf(rx, fm, fx);
        fy = fmaf(ry, fm, fy);
        fz = fmaf(rz, fm, fz);
        dv += fmaf(d, dfm, 3.f * fm);
    }

    // ---- reduction over 128 threads (4 warps) ----
    const unsigned m = 0xffffffffu;
#pragma unroll
    for (int o = 16; o; o >>= 1) {
        fx += __shfl_down_sync(m, fx, o);
        fy += __shfl_down_sync(m, fy, o);
        fz += __shfl_down_sync(m, fz, o);
        dv += __shfl_down_sync(m, dv, o);
    }
    const int warp = tid >> 5;
    const int lane = tid & 31;
    if (lane == 0) {
        red[warp][0] = fx; red[warp][1] = fy; red[warp][2] = fz; red[warp][3] = dv;
    }
    __syncthreads();
    if (tid < 16) {
        float v = red[tid & 3][tid >> 2];
        v += __shfl_down_sync(0xffffu, v, 1);
        v += __shfl_down_sync(0xffffu, v, 2);
        if ((tid & 3) == 0) res[tid >> 2] = v;
    }
    __syncthreads();
    if (tid == 0) {
        float* fo = out + b * (NP * ND) + i * 3;
        fo[0] = res[0]; fo[1] = res[1]; fo[2] = res[2];
        g_divpart[b * NP + i] = res[3];
        __threadfence();
        unsigned old = atomicInc(&g_count, NBLOCKS - 1);
        s_last = (old == NBLOCKS - 1) ? 1 : 0;
    }
    __syncthreads();

    // ---- last block: deterministic divergence reduction ----
    if (s_last) {
        __threadfence();
        const int bb = tid >> 4;   // 0..7
        const int l  = tid & 15;
        float v = 0.f;
#pragma unroll
        for (int c = 0; c < 32; c++)
            v += __ldcg(&g_divpart[bb * NP + l * 32 + c]);
#pragma unroll
        for (int o = 8; o; o >>= 1) v += __shfl_down_sync(m, v, o, 16);
        if (l == 0) out[NB * NP * ND + bb] = -v;
    }
}

extern "C" void kernel_launch(void* const* d_in, const int* in_sizes, int n_in,
                              void* d_out, int out_size)
{
    const float* t_in  = (const float*)d_in[0];
    const float* x     = (const float*)d_in[1];
    const float* mus   = (const float*)d_in[2];
    const float* nlg   = (const float*)d_in[3];
    const float* mus_t = (const float*)d_in[4];
    const float* nlg_t = (const float*)d_in[5];
    const float* W     = (const float*)d_in[6];
    const float* bias  = (const float*)d_in[7];
    const float* imp   = (const float*)d_in[8];
    float* out = (float*)d_out;

    build_table_kernel<<<NTAB / 256, TPB>>>(t_in, mus, nlg, mus_t, nlg_t, W, bias, imp);
    dim3 grid(NP, NB);
    pair_kernel<<<grid, TPB>>>(x, out);
}

// round 9
// speedup vs baseline: 2.9394x; 1.3617x over previous
#include <cuda_runtime.h>
#include <math.h>

#define NP 512
#define ND 3
#define NK 32
#define NT 10
#define NB 8
#define EPSF 1e-6f

#define NTAB 2048
#define DRANGE 4.0f
#define TSCALE ((float)NTAB / DRANGE)

#define PAIR_BLOCKS (NB * (NP / 32))   // 128 blocks, 32 warps each, warp-per-i
#define PTPB 1024

__device__ float4   g_qtab[NTAB];        // (fm_i, dfm_i, fm_{i+1}, dfm_{i+1})
__device__ float    g_divpart[NB * NP];
__device__ unsigned g_count = 0;

// ---- launch 1: 16 blocks x 128 thr; each block redundantly computes weights,
//      each thread fills one quad entry (evaluates two grid points) ----
__global__ void __launch_bounds__(128) build_table_kernel(
    const float* __restrict__ t_in,
    const float* __restrict__ mus,
    const float* __restrict__ nlg,
    const float* __restrict__ mus_t,
    const float* __restrict__ nlg_t,
    const float* __restrict__ W,
    const float* __restrict__ bias,
    const float* __restrict__ imp)
{
    __shared__ float s_mu[NK], s_ig2[NK], s_w[NK];
    __shared__ float s_cadd;

    const int tid = threadIdx.x;

    if (tid < NK) {
        const int k = tid;
        const float t = t_in[0];
        float tr[NT];
        float ssum = 0.f;
#pragma unroll
        for (int q = 0; q < NT; q++) {
            float ig = __expf(nlg_t[q]);
            float df = t - mus_t[q];
            float v  = __expf(-df * df * ig * ig);
            tr[q] = v;
            ssum += v;
        }
        const float invs = 1.0f / (EPSF + ssum);

        float w = 0.f;
#pragma unroll
        for (int q = 0; q < NT; q++) w = fmaf(W[k * NT + q], tr[q], w);
        w *= invs;

        float v = imp[k] * imp[k] * w;
#pragma unroll
        for (int o = 16; o; o >>= 1) v += __shfl_down_sync(0xffffffffu, v, o);

        float ig = __expf(nlg[k]);
        s_mu[k]  = mus[k];
        s_ig2[k] = ig * ig;
        s_w[k]   = w;
        if (k == 0) {
            float cadd = v;
#pragma unroll
            for (int q = 0; q < NT; q++) cadd = fmaf(bias[q] * invs, tr[q], cadd);
            s_cadd = cadd;
        }
    }
    __syncthreads();

    const float cadd = s_cadd;
    const int idx = blockIdx.x * 128 + tid;   // 0..2047

    float fm01[2], dfm01[2];
#pragma unroll
    for (int h = 0; h < 2; h++) {
        const float d = (float)(idx + h) * (DRANGE / (float)NTAB);
        float S0 = 0.f, W0 = 0.f, SD = 0.f, SDW = 0.f;
#pragma unroll 8
        for (int k = 0; k < NK; k++) {
            float diff = d - s_mu[k];
            float ig2  = s_ig2[k];
            float r  = __expf(-diff * diff * ig2);
            float dr = -2.f * diff * ig2 * r;
            S0  += r;
            W0   = fmaf(r,  s_w[k], W0);
            SD  += dr;
            SDW  = fmaf(dr, s_w[k], SDW);
        }
        const float inv = 1.0f / (EPSF + S0);
        fm01[h]  = fmaf(W0, inv, cadd);
        dfm01[h] = (SDW - W0 * SD * inv) * inv;
    }
    float4 q;
    q.x = fm01[0]; q.y = dfm01[0]; q.z = fm01[1]; q.w = dfm01[1];
    g_qtab[idx] = q;
}

// ---- launch 2: pair kernel. 128 blocks x 1024 thr; warp w = target i ----
__global__ void __launch_bounds__(PTPB) pair_kernel(const float* __restrict__ x,
                                                    float* __restrict__ out)
{
    __shared__ float4 s_tab[NTAB];    // 32 KB
    __shared__ float4 s_pos[NP];      // 8 KB
    __shared__ int    s_last;

    const int tid  = threadIdx.x;
    const int bid  = blockIdx.x;
    const int b    = bid >> 4;              // batch
    const int ibase = (bid & 15) * 32;      // i-chunk
    const int warp = tid >> 5;
    const int lane = tid & 31;

    // fill table (coherent coalesced loads from previous launch's writes)
    {
        const float4* gt = g_qtab;
#pragma unroll
        for (int q = 0; q < NTAB / PTPB; q++)
            s_tab[q * PTPB + tid] = __ldg(&gt[q * PTPB + tid]);
    }
    // fill positions, padded to float4
    if (tid < NP) {
        const float* xb = x + b * (NP * ND) + tid * 3;
        float4 p;
        p.x = xb[0]; p.y = xb[1]; p.z = xb[2]; p.w = 0.f;
        s_pos[tid] = p;
    }
    __syncthreads();

    const int i = ibase + warp;
    const float4 pi = s_pos[i];

    float fx = 0.f, fy = 0.f, fz = 0.f, dv = 0.f;

#pragma unroll 4
    for (int it = 0; it < NP / 32; it++) {
        const int j = it * 32 + lane;
        const float4 pj = s_pos[j];
        const float rx = pi.x - pj.x;
        const float ry = pi.y - pj.y;
        const float rz = pi.z - pj.z;
        float d2s = fmaf(rx, rx, fmaf(ry, ry, fmaf(rz, rz, EPSF)));
        float d;
        asm("sqrt.approx.ftz.f32 %0, %1;" : "=f"(d) : "f"(d2s));

        float u = d * TSCALE;
        int i0 = (int)u;
        i0 = min(i0, NTAB - 1);
        float frac = u - (float)i0;
        const float4 q = s_tab[i0];
        float fm  = fmaf(frac, q.z - q.x, q.x);
        float dfm = fmaf(frac, q.w - q.y, q.y);

        if (j == i) { fm = 0.f; dfm = 0.f; }   // remove_diagonal

        fx = fmaf(rx, fm, fx);
        fy = fmaf(ry, fm, fy);
        fz = fmaf(rz, fm, fz);
        dv += fmaf(d, dfm, 3.f * fm);
    }

    // warp-level reduction only
    const unsigned m = 0xffffffffu;
#pragma unroll
    for (int o = 16; o; o >>= 1) {
        fx += __shfl_down_sync(m, fx, o);
        fy += __shfl_down_sync(m, fy, o);
        fz += __shfl_down_sync(m, fz, o);
        dv += __shfl_down_sync(m, dv, o);
    }
    if (lane == 0) {
        float* fo = out + b * (NP * ND) + i * 3;
        fo[0] = fx; fo[1] = fy; fo[2] = fz;
        g_divpart[b * NP + i] = dv;
    }
    __threadfence();
    __syncthreads();

    if (tid == 0) {
        unsigned old = atomicInc(&g_count, PAIR_BLOCKS - 1);
        s_last = (old == PAIR_BLOCKS - 1) ? 1 : 0;
    }
    __syncthreads();

    // ---- last block: deterministic divergence reduction ----
    if (s_last) {
        __threadfence();
        if (tid < 256) {
            const int bb = tid >> 5;   // warp -> batch (8 warps)
            const int l  = tid & 31;
            float v = 0.f;
#pragma unroll
            for (int c = 0; c < 16; c++)
                v += __ldcg(&g_divpart[bb * NP + l * 16 + c]);
#pragma unroll
            for (int o = 16; o; o >>= 1) v += __shfl_down_sync(m, v, o);
            if (l == 0) out[NB * NP * ND + bb] = -v;
        }
    }
}

extern "C" void kernel_launch(void* const* d_in, const int* in_sizes, int n_in,
                              void* d_out, int out_size)
{
    const float* t_in  = (const float*)d_in[0];
    const float* x     = (const float*)d_in[1];
    const float* mus   = (const float*)d_in[2];
    const float* nlg   = (const float*)d_in[3];
    const float* mus_t = (const float*)d_in[4];
    const float* nlg_t = (const float*)d_in[5];
    const float* W     = (const float*)d_in[6];
    const float* bias  = (const float*)d_in[7];
    const float* imp   = (const float*)d_in[8];
    float* out = (float*)d_out;

    build_table_kernel<<<NTAB / 128, 128>>>(t_in, mus, nlg, mus_t, nlg_t, W, bias, imp);
    pair_kernel<<<PAIR_BLOCKS, PTPB>>>(x, out);
}